// round 7
// baseline (speedup 1.0000x reference)
#include <cuda_runtime.h>
#include <cuda_bf16.h>
#include <math.h>

// ---------------- problem constants ----------------
#define Bn   8
#define Ln   512
#define DM   512          // d_model
#define DI   1024         // d_inner
#define DS   16           // d_state
#define DTR  32           // dt_rank
#define NL   4            // n_layers
#define HOR  96           // horizon
#define DCONV 4
#define MROWS (Bn * Ln)   // 4096
#define EPSV 1e-5f

// ---------------- scratch buffers (device globals: allocation-free) ----------------
__device__ float g_h[MROWS * DM];        // residual stream
__device__ float g_hn[MROWS * DM];       // rmsnorm output
__device__ float g_xz[MROWS * 2 * DI];   // in_proj output (x | z)
__device__ float g_xin[MROWS * DI];      // conv+silu output
__device__ float g_dbc[MROWS * 64];      // x_proj output (dt_r | B | C)
__device__ float g_delta[MROWS * DI];    // softplus(dt)
__device__ float g_y[MROWS * DI];        // scan output

// ---------------- packed f32x2 helpers (FFMA2 path, 2x fp32 FMA rate) -------------
__device__ __forceinline__ unsigned long long pack2(float lo, float hi) {
    unsigned long long r;
    asm("mov.b64 %0, {%1, %2};" : "=l"(r) : "f"(lo), "f"(hi));
    return r;
}
__device__ __forceinline__ void ffma2(unsigned long long& d,
                                      unsigned long long a,
                                      unsigned long long b) {
    asm("fma.rn.f32x2 %0, %1, %2, %0;" : "+l"(d) : "l"(a), "l"(b));
}
__device__ __forceinline__ float2 unpack2(unsigned long long v) {
    float2 f;
    asm("mov.b64 {%0, %1}, %2;" : "=f"(f.x), "=f"(f.y) : "l"(v));
    return f;
}

__device__ __forceinline__ float sigmoidf_(float x) { return 1.0f / (1.0f + expf(-x)); }
__device__ __forceinline__ float siluf_(float x)    { return x * sigmoidf_(x); }
__device__ __forceinline__ float softplusf_(float x) {
    return (x > 20.0f) ? x : log1pf(expf(x));
}

// ---------------- embed: h[row, d] = x[row] * ew[d] + eb[d] ----------------
__global__ void embed_kernel(const float* __restrict__ x,
                             const float* __restrict__ ew,
                             const float* __restrict__ eb) {
    int t = blockIdx.x * blockDim.x + threadIdx.x;
    if (t >= MROWS * DM) return;
    int row = t >> 9;          // / DM
    int d   = t & (DM - 1);
    g_h[t] = x[row] * ew[d] + eb[d];
}

// ---------------- rmsnorm: one block per row ----------------
__global__ void rmsnorm_kernel(const float* __restrict__ w) {
    int row = blockIdx.x;
    const float* hr = g_h + (size_t)row * DM;
    float s = 0.0f;
    for (int d = threadIdx.x; d < DM; d += 256) {
        float v = hr[d];
        s += v * v;
    }
    #pragma unroll
    for (int off = 16; off > 0; off >>= 1)
        s += __shfl_xor_sync(0xffffffffu, s, off);
    __shared__ float red[8];
    __shared__ float scale_s;
    int lane = threadIdx.x & 31, wid = threadIdx.x >> 5;
    if (lane == 0) red[wid] = s;
    __syncthreads();
    if (threadIdx.x == 0) {
        float t = 0.0f;
        #pragma unroll
        for (int i = 0; i < 8; i++) t += red[i];
        scale_s = rsqrtf(t / (float)DM + EPSV);
    }
    __syncthreads();
    float sc = scale_s;
    for (int d = threadIdx.x; d < DM; d += 256)
        g_hn[(size_t)row * DM + d] = hr[d] * sc * w[d];
}

// ---------------- SGEMM: C[M,N] = A[M,K] @ W[N,K]^T (+ epilogue) ----------------
// EPI 0: plain store.  EPI 1: softplus(v + bias[n]).  EPI 2: C += v (residual).
#define BMT 128
#define BNT 128
#define BKT 16
#define SMS (BMT + 4)

template <int EPI>
__global__ __launch_bounds__(256)
void sgemm_kernel(const float* __restrict__ A, int lda,
                  const float* __restrict__ W, int ldw,
                  float* __restrict__ C, int ldc,
                  int N, int K,
                  const float* __restrict__ bias) {
    __shared__ float As[BKT][SMS];
    __shared__ float Ws[BKT][SMS];
    const int tid = threadIdx.x;
    const int bm = blockIdx.y * BMT;
    const int bn = blockIdx.x * BNT;
    const int tm = (tid >> 4) * 8;
    const int tn = (tid & 15) * 8;

    unsigned long long acc[8][4];
    #pragma unroll
    for (int i = 0; i < 8; i++)
        #pragma unroll
        for (int j = 0; j < 4; j++) acc[i][j] = 0ull;

    for (int k0 = 0; k0 < K; k0 += BKT) {
        #pragma unroll
        for (int it = 0; it < 2; it++) {
            int idx = tid + it * 256;        // 0..511
            int r   = idx >> 2;              // 0..127
            int c4  = (idx & 3) * 4;         // 0,4,8,12
            float4 av = *reinterpret_cast<const float4*>(
                &A[(size_t)(bm + r) * lda + k0 + c4]);
            As[c4 + 0][r] = av.x; As[c4 + 1][r] = av.y;
            As[c4 + 2][r] = av.z; As[c4 + 3][r] = av.w;
            float4 wv = make_float4(0.f, 0.f, 0.f, 0.f);
            if (bn + r < N)
                wv = *reinterpret_cast<const float4*>(
                    &W[(size_t)(bn + r) * ldw + k0 + c4]);
            Ws[c4 + 0][r] = wv.x; Ws[c4 + 1][r] = wv.y;
            Ws[c4 + 2][r] = wv.z; Ws[c4 + 3][r] = wv.w;
        }
        __syncthreads();
        #pragma unroll
        for (int k = 0; k < BKT; k++) {
            float a[8];
            *reinterpret_cast<float4*>(&a[0]) =
                *reinterpret_cast<const float4*>(&As[k][tm]);
            *reinterpret_cast<float4*>(&a[4]) =
                *reinterpret_cast<const float4*>(&As[k][tm + 4]);
            unsigned long long bp[4];
            #pragma unroll
            for (int j = 0; j < 4; j++)
                bp[j] = *reinterpret_cast<const unsigned long long*>(
                    &Ws[k][tn + 2 * j]);
            #pragma unroll
            for (int i = 0; i < 8; i++) {
                unsigned long long ad = pack2(a[i], a[i]);
                #pragma unroll
                for (int j = 0; j < 4; j++) ffma2(acc[i][j], ad, bp[j]);
            }
        }
        __syncthreads();
    }

    #pragma unroll
    for (int i = 0; i < 8; i++) {
        size_t rowoff = (size_t)(bm + tm + i) * ldc;
        #pragma unroll
        for (int j = 0; j < 4; j++) {
            float2 v = unpack2(acc[i][j]);
            int col = bn + tn + 2 * j;
            if (col < N) {
                if (EPI == 0) {
                    C[rowoff + col]     = v.x;
                    C[rowoff + col + 1] = v.y;
                } else if (EPI == 1) {
                    C[rowoff + col]     = softplusf_(v.x + bias[col]);
                    C[rowoff + col + 1] = softplusf_(v.y + bias[col + 1]);
                } else {
                    C[rowoff + col]     += v.x;
                    C[rowoff + col + 1] += v.y;
                }
            }
        }
    }
}

// ---------------- causal depthwise conv (D_CONV=4) + silu ----------------
__global__ void conv_silu_kernel(const float* __restrict__ cw,
                                 const float* __restrict__ cb) {
    int t = blockIdx.x * blockDim.x + threadIdx.x;
    if (t >= MROWS * DI) return;
    int row = t >> 10;         // b*L + l
    int c   = t & (DI - 1);
    int l   = row & (Ln - 1);
    float s = cb[c];
    const float* w = cw + (size_t)c * DCONV;
    #pragma unroll
    for (int j = 0; j < DCONV; j++) {
        int ll = l - (DCONV - 1) + j;
        if (ll >= 0)
            s = fmaf(w[j], g_xz[(size_t)(row - (DCONV - 1 - j)) * (2 * DI) + c], s);
    }
    g_xin[t] = siluf_(s);
}

// ---------------- selective scan: 16 lanes (states) per (b, channel) ----------------
__global__ void scan_kernel(const float* __restrict__ A_log,
                            const float* __restrict__ Dvec) {
    int t = blockIdx.x * blockDim.x + threadIdx.x;
    int pair = t >> 4;                   // b*DI + c
    int n    = t & 15;                   // state index
    if (pair >= Bn * DI) return;
    int b = pair >> 10;
    int c = pair & (DI - 1);

    float Ac = -expf(A_log[(size_t)c * DS + n]);
    float Dc = Dvec[c];

    const float* drow   = g_delta + (size_t)b * Ln * DI + c;
    const float* xrow   = g_xin   + (size_t)b * Ln * DI + c;
    const float* dbcrow = g_dbc   + (size_t)b * Ln * 64;
    const float* zrow   = g_xz    + (size_t)b * Ln * (2 * DI) + DI + c;
    float*       yrow   = g_y     + (size_t)b * Ln * DI + c;

    float h = 0.0f;
    for (int l = 0; l < Ln; l++) {
        float dt = drow[(size_t)l * DI];
        float xv = xrow[(size_t)l * DI];
        float Bv = dbcrow[(size_t)l * 64 + DTR + n];
        float Cv = dbcrow[(size_t)l * 64 + DTR + DS + n];
        float a  = expf(dt * Ac);
        h = fmaf(a, h, dt * Bv * xv);
        float p = h * Cv;
        p += __shfl_xor_sync(0xffffffffu, p, 8);
        p += __shfl_xor_sync(0xffffffffu, p, 4);
        p += __shfl_xor_sync(0xffffffffu, p, 2);
        p += __shfl_xor_sync(0xffffffffu, p, 1);
        if (n == 0) {
            float zv = zrow[(size_t)l * (2 * DI)];
            float yv = fmaf(Dc, xv, p);
            yrow[(size_t)l * DI] = yv * siluf_(zv);
        }
    }
}

// ---------------- head: out[b, h] = h_last[b] . head_w[h] + head_b[h] ----------------
__global__ void head_kernel(const float* __restrict__ hw,
                            const float* __restrict__ hb,
                            float* __restrict__ out) {
    int ob = blockIdx.x;               // 0 .. B*HOR-1
    int b  = ob / HOR;
    int hh = ob - b * HOR;
    const float* hr = g_h + (size_t)(b * Ln + Ln - 1) * DM;
    const float* wr = hw + (size_t)hh * DM;
    float s = 0.0f;
    for (int d = threadIdx.x; d < DM; d += 128) s = fmaf(hr[d], wr[d], s);
    #pragma unroll
    for (int off = 16; off > 0; off >>= 1)
        s += __shfl_xor_sync(0xffffffffu, s, off);
    __shared__ float red[4];
    int lane = threadIdx.x & 31, wid = threadIdx.x >> 5;
    if (lane == 0) red[wid] = s;
    __syncthreads();
    if (threadIdx.x == 0)
        out[ob] = red[0] + red[1] + red[2] + red[3] + hb[hh];
}

// ---------------- launcher ----------------
extern "C" void kernel_launch(void* const* d_in, const int* in_sizes, int n_in,
                              void* d_out, int out_size) {
    const float* x        = (const float*)d_in[0];
    const float* embed_w  = (const float*)d_in[1];
    const float* embed_b  = (const float*)d_in[2];
    const float* norm_w   = (const float*)d_in[3];
    const float* in_w     = (const float*)d_in[4];
    const float* conv_w   = (const float*)d_in[5];
    const float* conv_b   = (const float*)d_in[6];
    const float* xproj_w  = (const float*)d_in[7];
    const float* dt_w     = (const float*)d_in[8];
    const float* dt_b     = (const float*)d_in[9];
    const float* A_log    = (const float*)d_in[10];
    const float* Dvec     = (const float*)d_in[11];
    const float* out_w    = (const float*)d_in[12];
    const float* head_w   = (const float*)d_in[13];
    const float* head_b   = (const float*)d_in[14];
    float* out = (float*)d_out;

    // device-global scratch addresses (query is not a stream op; capture-safe)
    void* p;
    cudaGetSymbolAddress(&p, g_hn);    float* phn    = (float*)p;
    cudaGetSymbolAddress(&p, g_h);     float* ph     = (float*)p;
    cudaGetSymbolAddress(&p, g_xz);    float* pxz    = (float*)p;
    cudaGetSymbolAddress(&p, g_xin);   float* pxin   = (float*)p;
    cudaGetSymbolAddress(&p, g_dbc);   float* pdbc   = (float*)p;
    cudaGetSymbolAddress(&p, g_delta); float* pdelta = (float*)p;
    cudaGetSymbolAddress(&p, g_y);     float* py     = (float*)p;

    embed_kernel<<<(MROWS * DM + 255) / 256, 256>>>(x, embed_w, embed_b);

    for (int i = 0; i < NL; i++) {
        rmsnorm_kernel<<<MROWS, 256>>>(norm_w + (size_t)i * DM);

        // xz = hn @ in_w^T      M=4096 N=2048 K=512
        sgemm_kernel<0><<<dim3(2 * DI / BNT, MROWS / BMT), 256>>>(
            phn, DM, in_w + (size_t)i * 2 * DI * DM, DM,
            pxz, 2 * DI, 2 * DI, DM, nullptr);

        conv_silu_kernel<<<(MROWS * DI + 255) / 256, 256>>>(
            conv_w + (size_t)i * DI * DCONV, conv_b + (size_t)i * DI);

        // dbc = xin @ xproj_w^T   M=4096 N=64 K=1024
        sgemm_kernel<0><<<dim3(1, MROWS / BMT), 256>>>(
            pxin, DI, xproj_w + (size_t)i * 64 * DI, DI,
            pdbc, 64, 64, DI, nullptr);

        // delta = softplus(dbc[:, :32] @ dt_w^T + dt_b)   M=4096 N=1024 K=32
        sgemm_kernel<1><<<dim3(DI / BNT, MROWS / BMT), 256>>>(
            pdbc, 64, dt_w + (size_t)i * DI * DTR, DTR,
            pdelta, DI, DI, DTR, dt_b + (size_t)i * DI);

        // selective scan + gating -> y
        scan_kernel<<<(Bn * DI * DS) / 256, 256>>>(
            A_log + (size_t)i * DI * DS, Dvec + (size_t)i * DI);

        // h += y @ out_w^T   M=4096 N=512 K=1024  (residual epilogue)
        sgemm_kernel<2><<<dim3(DM / BNT, MROWS / BMT), 256>>>(
            py, DI, out_w + (size_t)i * DM * DI, DI,
            ph, DM, DM, DI, nullptr);
    }

    head_kernel<<<Bn * HOR, 128>>>(head_w, head_b, out);
}

// round 8
// speedup vs baseline: 1.0005x; 1.0005x over previous
#include <cuda_runtime.h>
#include <cuda_bf16.h>
#include <math.h>

// ---------------- problem constants ----------------
#define Bn   8
#define Ln   512
#define DM   512          // d_model
#define DI   1024         // d_inner
#define DS   16           // d_state
#define DTR  32           // dt_rank
#define NL   4            // n_layers
#define HOR  96           // horizon
#define DCONV 4
#define MROWS (Bn * Ln)   // 4096
#define EPSV 1e-5f

// ---------------- scratch buffers (device globals: allocation-free) ----------------
__device__ float g_h[MROWS * DM];        // residual stream
__device__ float g_hn[MROWS * DM];       // rmsnorm output
__device__ float g_xz[MROWS * 2 * DI];   // in_proj output (x | z)
__device__ float g_xin[MROWS * DI];      // conv+silu output
__device__ float g_dbc[MROWS * 64];      // x_proj output (dt_r | B | C)
__device__ float g_delta[MROWS * DI];    // softplus(dt)
__device__ float g_y[MROWS * DI];        // scan output

// ---------------- packed f32x2 helpers (FFMA2 path, 2x fp32 FMA rate) -------------
__device__ __forceinline__ unsigned long long pack2(float lo, float hi) {
    unsigned long long r;
    asm("mov.b64 %0, {%1, %2};" : "=l"(r) : "f"(lo), "f"(hi));
    return r;
}
__device__ __forceinline__ void ffma2(unsigned long long& d,
                                      unsigned long long a,
                                      unsigned long long b) {
    asm("fma.rn.f32x2 %0, %1, %2, %0;" : "+l"(d) : "l"(a), "l"(b));
}
__device__ __forceinline__ float2 unpack2(unsigned long long v) {
    float2 f;
    asm("mov.b64 {%0, %1}, %2;" : "=f"(f.x), "=f"(f.y) : "l"(v));
    return f;
}

__device__ __forceinline__ float sigmoidf_(float x) { return 1.0f / (1.0f + expf(-x)); }
__device__ __forceinline__ float siluf_(float x)    { return x * sigmoidf_(x); }
__device__ __forceinline__ float softplusf_(float x) {
    return (x > 20.0f) ? x : log1pf(expf(x));
}

// ---------------- embed: h[row, d] = x[row] * ew[d] + eb[d] ----------------
__global__ void embed_kernel(const float* __restrict__ x,
                             const float* __restrict__ ew,
                             const float* __restrict__ eb) {
    int t = blockIdx.x * blockDim.x + threadIdx.x;
    if (t >= MROWS * DM) return;
    int row = t >> 9;          // / DM
    int d   = t & (DM - 1);
    g_h[t] = x[row] * ew[d] + eb[d];
}

// ---------------- rmsnorm: one block per row ----------------
__global__ void rmsnorm_kernel(const float* __restrict__ w) {
    int row = blockIdx.x;
    const float* hr = g_h + (size_t)row * DM;
    float s = 0.0f;
    for (int d = threadIdx.x; d < DM; d += 256) {
        float v = hr[d];
        s += v * v;
    }
    #pragma unroll
    for (int off = 16; off > 0; off >>= 1)
        s += __shfl_xor_sync(0xffffffffu, s, off);
    __shared__ float red[8];
    __shared__ float scale_s;
    int lane = threadIdx.x & 31, wid = threadIdx.x >> 5;
    if (lane == 0) red[wid] = s;
    __syncthreads();
    if (threadIdx.x == 0) {
        float t = 0.0f;
        #pragma unroll
        for (int i = 0; i < 8; i++) t += red[i];
        scale_s = rsqrtf(t / (float)DM + EPSV);
    }
    __syncthreads();
    float sc = scale_s;
    for (int d = threadIdx.x; d < DM; d += 256)
        g_hn[(size_t)row * DM + d] = hr[d] * sc * w[d];
}

// ---------------- SGEMM: C[M,N] = A[M,K] @ W[N,K]^T (+ epilogue) ----------------
// EPI 0: plain store.  EPI 1: softplus(v + bias[n]).  EPI 2: C += v (residual).
#define BMT 128
#define BNT 128
#define BKT 16
#define SMS (BMT + 4)

template <int EPI>
__global__ __launch_bounds__(256)
void sgemm_kernel(const float* __restrict__ A, int lda,
                  const float* __restrict__ W, int ldw,
                  float* __restrict__ C, int ldc,
                  int N, int K,
                  const float* __restrict__ bias) {
    __shared__ float As[BKT][SMS];
    __shared__ float Ws[BKT][SMS];
    const int tid = threadIdx.x;
    const int bm = blockIdx.y * BMT;
    const int bn = blockIdx.x * BNT;
    const int tm = (tid >> 4) * 8;
    const int tn = (tid & 15) * 8;

    unsigned long long acc[8][4];
    #pragma unroll
    for (int i = 0; i < 8; i++)
        #pragma unroll
        for (int j = 0; j < 4; j++) acc[i][j] = 0ull;

    for (int k0 = 0; k0 < K; k0 += BKT) {
        #pragma unroll
        for (int it = 0; it < 2; it++) {
            int idx = tid + it * 256;        // 0..511
            int r   = idx >> 2;              // 0..127
            int c4  = (idx & 3) * 4;         // 0,4,8,12
            float4 av = *reinterpret_cast<const float4*>(
                &A[(size_t)(bm + r) * lda + k0 + c4]);
            As[c4 + 0][r] = av.x; As[c4 + 1][r] = av.y;
            As[c4 + 2][r] = av.z; As[c4 + 3][r] = av.w;
            float4 wv = make_float4(0.f, 0.f, 0.f, 0.f);
            if (bn + r < N)
                wv = *reinterpret_cast<const float4*>(
                    &W[(size_t)(bn + r) * ldw + k0 + c4]);
            Ws[c4 + 0][r] = wv.x; Ws[c4 + 1][r] = wv.y;
            Ws[c4 + 2][r] = wv.z; Ws[c4 + 3][r] = wv.w;
        }
        __syncthreads();
        #pragma unroll
        for (int k = 0; k < BKT; k++) {
            float a[8];
            *reinterpret_cast<float4*>(&a[0]) =
                *reinterpret_cast<const float4*>(&As[k][tm]);
            *reinterpret_cast<float4*>(&a[4]) =
                *reinterpret_cast<const float4*>(&As[k][tm + 4]);
            unsigned long long bp[4];
            #pragma unroll
            for (int j = 0; j < 4; j++)
                bp[j] = *reinterpret_cast<const unsigned long long*>(
                    &Ws[k][tn + 2 * j]);
            #pragma unroll
            for (int i = 0; i < 8; i++) {
                unsigned long long ad = pack2(a[i], a[i]);
                #pragma unroll
                for (int j = 0; j < 4; j++) ffma2(acc[i][j], ad, bp[j]);
            }
        }
        __syncthreads();
    }

    #pragma unroll
    for (int i = 0; i < 8; i++) {
        size_t rowoff = (size_t)(bm + tm + i) * ldc;
        #pragma unroll
        for (int j = 0; j < 4; j++) {
            float2 v = unpack2(acc[i][j]);
            int col = bn + tn + 2 * j;
            if (col < N) {
                if (EPI == 0) {
                    C[rowoff + col]     = v.x;
                    C[rowoff + col + 1] = v.y;
                } else if (EPI == 1) {
                    C[rowoff + col]     = softplusf_(v.x + bias[col]);
                    C[rowoff + col + 1] = softplusf_(v.y + bias[col + 1]);
                } else {
                    C[rowoff + col]     += v.x;
                    C[rowoff + col + 1] += v.y;
                }
            }
        }
    }
}

// ---------------- causal depthwise conv (D_CONV=4) + silu ----------------
__global__ void conv_silu_kernel(const float* __restrict__ cw,
                                 const float* __restrict__ cb) {
    int t = blockIdx.x * blockDim.x + threadIdx.x;
    if (t >= MROWS * DI) return;
    int row = t >> 10;         // b*L + l
    int c   = t & (DI - 1);
    int l   = row & (Ln - 1);
    float s = cb[c];
    const float* w = cw + (size_t)c * DCONV;
    #pragma unroll
    for (int j = 0; j < DCONV; j++) {
        int ll = l - (DCONV - 1) + j;
        if (ll >= 0)
            s = fmaf(w[j], g_xz[(size_t)(row - (DCONV - 1 - j)) * (2 * DI) + c], s);
    }
    g_xin[t] = siluf_(s);
}

// ---------------- selective scan: 16 lanes (states) per (b, channel) ----------------
__global__ void scan_kernel(const float* __restrict__ A_log,
                            const float* __restrict__ Dvec) {
    int t = blockIdx.x * blockDim.x + threadIdx.x;
    int pair = t >> 4;                   // b*DI + c
    int n    = t & 15;                   // state index
    if (pair >= Bn * DI) return;
    int b = pair >> 10;
    int c = pair & (DI - 1);

    float Ac = -expf(A_log[(size_t)c * DS + n]);
    float Dc = Dvec[c];

    const float* drow   = g_delta + (size_t)b * Ln * DI + c;
    const float* xrow   = g_xin   + (size_t)b * Ln * DI + c;
    const float* dbcrow = g_dbc   + (size_t)b * Ln * 64;
    const float* zrow   = g_xz    + (size_t)b * Ln * (2 * DI) + DI + c;
    float*       yrow   = g_y     + (size_t)b * Ln * DI + c;

    float h = 0.0f;
    for (int l = 0; l < Ln; l++) {
        float dt = drow[(size_t)l * DI];
        float xv = xrow[(size_t)l * DI];
        float Bv = dbcrow[(size_t)l * 64 + DTR + n];
        float Cv = dbcrow[(size_t)l * 64 + DTR + DS + n];
        float a  = expf(dt * Ac);
        h = fmaf(a, h, dt * Bv * xv);
        float p = h * Cv;
        p += __shfl_xor_sync(0xffffffffu, p, 8);
        p += __shfl_xor_sync(0xffffffffu, p, 4);
        p += __shfl_xor_sync(0xffffffffu, p, 2);
        p += __shfl_xor_sync(0xffffffffu, p, 1);
        if (n == 0) {
            float zv = zrow[(size_t)l * (2 * DI)];
            float yv = fmaf(Dc, xv, p);
            yrow[(size_t)l * DI] = yv * siluf_(zv);
        }
    }
}

// ---------------- head: out[b, h] = h_last[b] . head_w[h] + head_b[h] ----------------
__global__ void head_kernel(const float* __restrict__ hw,
                            const float* __restrict__ hb,
                            float* __restrict__ out) {
    int ob = blockIdx.x;               // 0 .. B*HOR-1
    int b  = ob / HOR;
    int hh = ob - b * HOR;
    const float* hr = g_h + (size_t)(b * Ln + Ln - 1) * DM;
    const float* wr = hw + (size_t)hh * DM;
    float s = 0.0f;
    for (int d = threadIdx.x; d < DM; d += 128) s = fmaf(hr[d], wr[d], s);
    #pragma unroll
    for (int off = 16; off > 0; off >>= 1)
        s += __shfl_xor_sync(0xffffffffu, s, off);
    __shared__ float red[4];
    int lane = threadIdx.x & 31, wid = threadIdx.x >> 5;
    if (lane == 0) red[wid] = s;
    __syncthreads();
    if (threadIdx.x == 0)
        out[ob] = red[0] + red[1] + red[2] + red[3] + hb[hh];
}

// ---------------- launcher ----------------
extern "C" void kernel_launch(void* const* d_in, const int* in_sizes, int n_in,
                              void* d_out, int out_size) {
    const float* x        = (const float*)d_in[0];
    const float* embed_w  = (const float*)d_in[1];
    const float* embed_b  = (const float*)d_in[2];
    const float* norm_w   = (const float*)d_in[3];
    const float* in_w     = (const float*)d_in[4];
    const float* conv_w   = (const float*)d_in[5];
    const float* conv_b   = (const float*)d_in[6];
    const float* xproj_w  = (const float*)d_in[7];
    const float* dt_w     = (const float*)d_in[8];
    const float* dt_b     = (const float*)d_in[9];
    const float* A_log    = (const float*)d_in[10];
    const float* Dvec     = (const float*)d_in[11];
    const float* out_w    = (const float*)d_in[12];
    const float* head_w   = (const float*)d_in[13];
    const float* head_b   = (const float*)d_in[14];
    float* out = (float*)d_out;

    // device-global scratch addresses (query is not a stream op; capture-safe)
    void* p;
    cudaGetSymbolAddress(&p, g_hn);    float* phn    = (float*)p;
    cudaGetSymbolAddress(&p, g_h);     float* ph     = (float*)p;
    cudaGetSymbolAddress(&p, g_xz);    float* pxz    = (float*)p;
    cudaGetSymbolAddress(&p, g_xin);   float* pxin   = (float*)p;
    cudaGetSymbolAddress(&p, g_dbc);   float* pdbc   = (float*)p;
    cudaGetSymbolAddress(&p, g_delta); float* pdelta = (float*)p;
    cudaGetSymbolAddress(&p, g_y);     float* py     = (float*)p;

    embed_kernel<<<(MROWS * DM + 255) / 256, 256>>>(x, embed_w, embed_b);

    for (int i = 0; i < NL; i++) {
        rmsnorm_kernel<<<MROWS, 256>>>(norm_w + (size_t)i * DM);

        // xz = hn @ in_w^T      M=4096 N=2048 K=512
        sgemm_kernel<0><<<dim3(2 * DI / BNT, MROWS / BMT), 256>>>(
            phn, DM, in_w + (size_t)i * 2 * DI * DM, DM,
            pxz, 2 * DI, 2 * DI, DM, nullptr);

        conv_silu_kernel<<<(MROWS * DI + 255) / 256, 256>>>(
            conv_w + (size_t)i * DI * DCONV, conv_b + (size_t)i * DI);

        // dbc = xin @ xproj_w^T   M=4096 N=64 K=1024
        sgemm_kernel<0><<<dim3(1, MROWS / BMT), 256>>>(
            pxin, DI, xproj_w + (size_t)i * 64 * DI, DI,
            pdbc, 64, 64, DI, nullptr);

        // delta = softplus(dbc[:, :32] @ dt_w^T + dt_b)   M=4096 N=1024 K=32
        sgemm_kernel<1><<<dim3(DI / BNT, MROWS / BMT), 256>>>(
            pdbc, 64, dt_w + (size_t)i * DI * DTR, DTR,
            pdelta, DI, DI, DTR, dt_b + (size_t)i * DI);

        // selective scan + gating -> y
        scan_kernel<<<(Bn * DI * DS) / 256, 256>>>(
            A_log + (size_t)i * DI * DS, Dvec + (size_t)i * DI);

        // h += y @ out_w^T   M=4096 N=512 K=1024  (residual epilogue)
        sgemm_kernel<2><<<dim3(DM / BNT, MROWS / BMT), 256>>>(
            py, DI, out_w + (size_t)i * DM * DI, DI,
            ph, DM, DM, DI, nullptr);
    }

    head_kernel<<<Bn * HOR, 128>>>(head_w, head_b, out);
}